// round 1
// baseline (speedup 1.0000x reference)
#include <cuda_runtime.h>
#include <math.h>

#define N_ROWS 8192
#define DIM    256
#define BM     64
#define BN     128
#define BK     16
#define NTILES (N_ROWS / BN)     // 64
#define NCHUNK (DIM / BK)        // 16
#define NBLK   (N_ROWS / BM)     // 128
#define SCALE  28.85390081777927f   /* (1/0.05) * log2(e) */
#define LN2F   0.6931471805599453f

// ---------------- scratch (static device globals; no allocation) -------------
__device__ float g_q[N_ROWS * DIM];       // normalized logits
__device__ float g_k[N_ROWS * DIM];       // normalized labels
__device__ int   g_adv[N_ROWS];           // ad idx if valid else -1
__device__ float g_partial[NBLK];
__device__ float g_pcount[NBLK];

// ---------------- kernel 1: L2 normalize rows --------------------------------
__global__ void normalize_kernel(const float* __restrict__ logits,
                                 const float* __restrict__ labels) {
    int row = blockIdx.x;
    const float* src = blockIdx.y ? labels : logits;
    float*       dst = blockIdx.y ? g_k    : g_q;
    int t = threadIdx.x;  // 64 threads, one float4 each
    float4 v = reinterpret_cast<const float4*>(src + (size_t)row * DIM)[t];
    float ss = v.x * v.x + v.y * v.y + v.z * v.z + v.w * v.w;
#pragma unroll
    for (int o = 16; o; o >>= 1) ss += __shfl_xor_sync(0xffffffffu, ss, o);
    __shared__ float ws[2];
    if ((t & 31) == 0) ws[t >> 5] = ss;
    __syncthreads();
    float tot = ws[0] + ws[1];
    float inv = 1.0f / fmaxf(sqrtf(tot), 1e-12f);
    v.x *= inv; v.y *= inv; v.z *= inv; v.w *= inv;
    reinterpret_cast<float4*>(dst + (size_t)row * DIM)[t] = v;
}

// ---------------- kernel 2: combined validity/ad index -----------------------
__global__ void adv_kernel(const int* __restrict__ pad, const int* __restrict__ ad) {
    int i = blockIdx.x * blockDim.x + threadIdx.x;
    if (i < N_ROWS) g_adv[i] = pad[i] ? ad[i] : -1;
}

// ---------------- kernel 3: fused GEMM + masked logsumexp --------------------
// Block: 256 threads = 16x16; thread (tx,ty) owns rows ty*4..+3, cols tx*8..+7
// of a 64x128 tile. Each block sweeps all 64 column tiles for its row band.
__global__ __launch_bounds__(256, 1) void main_kernel() {
    __shared__ float qs[2][BK][BM];    // k-major
    __shared__ float ks[2][BK][BN];    // k-major
    __shared__ int   adv_s[BN];
    __shared__ float rloss[BM];
    __shared__ float rc[BM];

    const int t  = threadIdx.x;
    const int tx = t & 15;
    const int ty = t >> 4;
    const int brow = blockIdx.x * BM;

    int adi[4];
#pragma unroll
    for (int i = 0; i < 4; i++) adi[i] = g_adv[brow + ty * 4 + i];

    float sA[4] = {0.f, 0.f, 0.f, 0.f};
    float sP[4] = {0.f, 0.f, 0.f, 0.f};

    // staging-register load indices (global -> regs -> smem transpose)
    const int qn = t >> 2;               // 0..63
    const int qk = (t & 3) << 2;         // 0,4,8,12
    const int kn0 = t >> 2;              // 0..63
    const int kn1 = kn0 + 64;            // 64..127
    const float* qbase = g_q + (size_t)(brow + qn) * DIM + qk;

    for (int jt = 0; jt < NTILES; jt++) {
        const int jcol = jt * BN;
        __syncthreads();  // previous tile epilogue done before adv_s rewrite
        if (t < BN) adv_s[t] = g_adv[jcol + t];

        const float* kbase0 = g_k + (size_t)(jcol + kn0) * DIM + qk;
        const float* kbase1 = g_k + (size_t)(jcol + kn1) * DIM + qk;

        float acc[4][8];
#pragma unroll
        for (int i = 0; i < 4; i++)
#pragma unroll
            for (int j = 0; j < 8; j++) acc[i][j] = 0.f;

        float4 qreg  = *reinterpret_cast<const float4*>(qbase);
        float4 kreg0 = *reinterpret_cast<const float4*>(kbase0);
        float4 kreg1 = *reinterpret_cast<const float4*>(kbase1);

        for (int c = 0; c < NCHUNK; c++) {
            const int buf = c & 1;
            // transpose-store staged chunk c
            qs[buf][qk + 0][qn] = qreg.x;
            qs[buf][qk + 1][qn] = qreg.y;
            qs[buf][qk + 2][qn] = qreg.z;
            qs[buf][qk + 3][qn] = qreg.w;
            ks[buf][qk + 0][kn0] = kreg0.x;
            ks[buf][qk + 1][kn0] = kreg0.y;
            ks[buf][qk + 2][kn0] = kreg0.z;
            ks[buf][qk + 3][kn0] = kreg0.w;
            ks[buf][qk + 0][kn1] = kreg1.x;
            ks[buf][qk + 1][kn1] = kreg1.y;
            ks[buf][qk + 2][kn1] = kreg1.z;
            ks[buf][qk + 3][kn1] = kreg1.w;
            __syncthreads();
            if (c + 1 < NCHUNK) {  // prefetch chunk c+1 while computing c
                qreg  = *reinterpret_cast<const float4*>(qbase  + (c + 1) * BK);
                kreg0 = *reinterpret_cast<const float4*>(kbase0 + (c + 1) * BK);
                kreg1 = *reinterpret_cast<const float4*>(kbase1 + (c + 1) * BK);
            }
#pragma unroll
            for (int k = 0; k < BK; k++) {
                float4 qf  = *reinterpret_cast<const float4*>(&qs[buf][k][ty * 4]);
                float4 kf0 = *reinterpret_cast<const float4*>(&ks[buf][k][tx * 8]);
                float4 kf1 = *reinterpret_cast<const float4*>(&ks[buf][k][tx * 8 + 4]);
                const float qv[4] = {qf.x, qf.y, qf.z, qf.w};
                const float kv[8] = {kf0.x, kf0.y, kf0.z, kf0.w,
                                     kf1.x, kf1.y, kf1.z, kf1.w};
#pragma unroll
                for (int i = 0; i < 4; i++)
#pragma unroll
                    for (int j = 0; j < 8; j++)
                        acc[i][j] = fmaf(qv[i], kv[j], acc[i][j]);
            }
        }
        // epilogue: exp2 + masked accumulate (implicit max = 0, values bounded)
#pragma unroll
        for (int j = 0; j < 8; j++) {
            const int   aj = adv_s[tx * 8 + j];
            const float va = (aj >= 0) ? 1.f : 0.f;
#pragma unroll
            for (int i = 0; i < 4; i++) {
                float e = exp2f(acc[i][j] * SCALE);
                sA[i] = fmaf(va, e, sA[i]);
                sP[i] += (aj == adi[i]) ? e : 0.f;
            }
        }
    }

    // reduce s over the 16 lanes (tx) that share each row
#pragma unroll
    for (int o = 1; o < 16; o <<= 1) {
#pragma unroll
        for (int i = 0; i < 4; i++) {
            sA[i] += __shfl_xor_sync(0xffffffffu, sA[i], o);
            sP[i] += __shfl_xor_sync(0xffffffffu, sP[i], o);
        }
    }
    if (tx == 0) {
#pragma unroll
        for (int i = 0; i < 4; i++) {
            int r = ty * 4 + i;
            float li = 0.f, ci = 0.f;
            if (adi[i] >= 0) {  // valid row => has_pos (diagonal is a positive)
                li = (log2f(sA[i]) - log2f(sP[i])) * LN2F;
                ci = 1.f;
            }
            rloss[r] = li;
            rc[r] = ci;
        }
    }
    __syncthreads();
    __shared__ float tl[2], tc[2];
    if (t < 64) {
        float l = rloss[t], c = rc[t];
#pragma unroll
        for (int o = 16; o; o >>= 1) {
            l += __shfl_xor_sync(0xffffffffu, l, o);
            c += __shfl_xor_sync(0xffffffffu, c, o);
        }
        if ((t & 31) == 0) { tl[t >> 5] = l; tc[t >> 5] = c; }
    }
    __syncthreads();
    if (t == 0) {
        g_partial[blockIdx.x] = tl[0] + tl[1];
        g_pcount[blockIdx.x]  = tc[0] + tc[1];
    }
}

// ---------------- kernel 4: finalize -----------------------------------------
__global__ void finalize_kernel(float* __restrict__ out) {
    int t = threadIdx.x;  // 128
    float s = g_partial[t];
    float c = g_pcount[t];
#pragma unroll
    for (int o = 16; o; o >>= 1) {
        s += __shfl_xor_sync(0xffffffffu, s, o);
        c += __shfl_xor_sync(0xffffffffu, c, o);
    }
    __shared__ float ss[4], cc[4];
    if ((t & 31) == 0) { ss[t >> 5] = s; cc[t >> 5] = c; }
    __syncthreads();
    if (t == 0) {
        float S = ss[0] + ss[1] + ss[2] + ss[3];
        float C = cc[0] + cc[1] + cc[2] + cc[3];
        out[0] = S / fmaxf(C, 1.0f);
    }
}

// ---------------- launch ------------------------------------------------------
extern "C" void kernel_launch(void* const* d_in, const int* in_sizes, int n_in,
                              void* d_out, int out_size) {
    const float* logits = (const float*)d_in[0];
    const float* labels = (const float*)d_in[1];
    const int*   pad    = (const int*)d_in[2];
    const int*   ad     = (const int*)d_in[3];

    normalize_kernel<<<dim3(N_ROWS, 2), 64>>>(logits, labels);
    adv_kernel<<<N_ROWS / 256, 256>>>(pad, ad);
    main_kernel<<<NBLK, 256>>>();
    finalize_kernel<<<1, 128>>>((float*)d_out);
}

// round 3
// speedup vs baseline: 4.8091x; 4.8091x over previous
#include <cuda_runtime.h>
#include <cuda_bf16.h>
#include <cstdint>
#include <math.h>

#define N_ROWS 8192
#define DIM    256
#define SCALE  28.85390081777927f   /* (1/0.05) * log2(e) */
#define LN2F   0.6931471805599453f

#define BMROW  128      /* rows per CTA  */
#define BNCOL  128      /* cols per output tile */
#define KC     64       /* k elements per chunk (128B rows) */
#define NCH    12       /* 768 / 64 */
#define NTILE  32       /* 4096 / 128 col tiles per CTA */

#define A_BUF_BYTES 16384
#define SM_A0   0
#define SM_B0   32768
#define SM_ADV  65536
#define SM_REDA 66048
#define SM_REDP 68096
#define DSMEM_BYTES 70144

// ---------------- device scratch ---------------------------------------------
__device__ unsigned short g_qext[N_ROWS * 512];  // [hi(256) | lo(256)] bf16
__device__ unsigned short g_kext[N_ROWS * 512];
__device__ int   g_adv[N_ROWS];
__device__ float g_rowA[2 * N_ROWS];
__device__ float g_rowP[2 * N_ROWS];
__device__ float g_partial[32];
__device__ float g_pcount[32];

__constant__ int c_cA[12] = {0,64,128,192,256,320,384,448,0,64,128,192};
__constant__ int c_cB[12] = {0,64,128,192,0,64,128,192,256,320,384,448};

// ---------------- PTX helpers ------------------------------------------------
__device__ __forceinline__ uint32_t smem_u32(const void* p) {
    uint32_t a;
    asm("{ .reg .u64 t; cvta.to.shared.u64 t, %1; cvt.u32.u64 %0, t; }" : "=r"(a) : "l"(p));
    return a;
}
__device__ __forceinline__ float fast_exp2(float x) {
    float y; asm("ex2.approx.ftz.f32 %0, %1;" : "=f"(y) : "f"(x)); return y;
}
#define CPA(dst, src) \
    asm volatile("cp.async.cg.shared.global [%0], [%1], 16;" :: "r"(dst), "l"(src) : "memory")
#define CPC() asm volatile("cp.async.commit_group;" ::: "memory")
#define CPW1() asm volatile("cp.async.wait_group 1;" ::: "memory")
#define CPW0() asm volatile("cp.async.wait_group 0;" ::: "memory")

#define LDSM4(r, a) \
    asm volatile("ldmatrix.sync.aligned.m8n8.x4.shared.b16 {%0,%1,%2,%3}, [%4];" \
                 : "=r"((r)[0]), "=r"((r)[1]), "=r"((r)[2]), "=r"((r)[3]) : "r"(a))

#define MMA16816(d, a, b0, b1) \
    asm volatile("mma.sync.aligned.m16n8k16.row.col.f32.bf16.bf16.f32 " \
                 "{%0,%1,%2,%3}, {%4,%5,%6,%7}, {%8,%9}, {%0,%1,%2,%3};" \
                 : "+f"((d)[0]), "+f"((d)[1]), "+f"((d)[2]), "+f"((d)[3]) \
                 : "r"((a)[0]), "r"((a)[1]), "r"((a)[2]), "r"((a)[3]), \
                   "r"(b0), "r"(b1))

// ---------------- kernel 1: normalize + bf16 hi/lo split ---------------------
__global__ void normalize_ext_kernel(const float* __restrict__ logits,
                                     const float* __restrict__ labels) {
    int row = blockIdx.x;
    const float* src = blockIdx.y ? labels : logits;
    unsigned short* dst = blockIdx.y ? g_kext : g_qext;
    int t = threadIdx.x;  // 64
    float4 v = reinterpret_cast<const float4*>(src + (size_t)row * DIM)[t];
    float ss = v.x * v.x + v.y * v.y + v.z * v.z + v.w * v.w;
#pragma unroll
    for (int o = 16; o; o >>= 1) ss += __shfl_xor_sync(0xffffffffu, ss, o);
    __shared__ float ws[2];
    if ((t & 31) == 0) ws[t >> 5] = ss;
    __syncthreads();
    float inv = 1.0f / fmaxf(sqrtf(ws[0] + ws[1]), 1e-12f);
    float f[4] = {v.x * inv, v.y * inv, v.z * inv, v.w * inv};
    unsigned short hi[4], lo[4];
#pragma unroll
    for (int i = 0; i < 4; i++) {
        __nv_bfloat16 h = __float2bfloat16(f[i]);
        hi[i] = *reinterpret_cast<unsigned short*>(&h);
        __nv_bfloat16 l = __float2bfloat16(f[i] - __bfloat162float(h));
        lo[i] = *reinterpret_cast<unsigned short*>(&l);
    }
    uint2 hv, lv;
    hv.x = (uint32_t)hi[0] | ((uint32_t)hi[1] << 16);
    hv.y = (uint32_t)hi[2] | ((uint32_t)hi[3] << 16);
    lv.x = (uint32_t)lo[0] | ((uint32_t)lo[1] << 16);
    lv.y = (uint32_t)lo[2] | ((uint32_t)lo[3] << 16);
    unsigned short* base = dst + (size_t)row * 512;
    *reinterpret_cast<uint2*>(base + 4 * t) = hv;
    *reinterpret_cast<uint2*>(base + 256 + 4 * t) = lv;
}

// ---------------- kernel 2: validity/ad --------------------------------------
__global__ void adv_kernel(const int* __restrict__ pad, const int* __restrict__ ad) {
    int i = blockIdx.x * blockDim.x + threadIdx.x;
    if (i < N_ROWS) g_adv[i] = pad[i] ? ad[i] : -1;
}

// ---------------- chunk loaders (cp.async, XOR-swizzled smem) ----------------
__device__ __forceinline__ void load_chunk(uint32_t sm_base, int buf, int c,
                                           int brow, int cb0, int tid) {
    const int cA = c_cA[c], cB = c_cB[c];
    uint32_t aDst = sm_base + SM_A0 + (uint32_t)buf * A_BUF_BYTES;
    uint32_t bDst = sm_base + SM_B0 + (uint32_t)buf * A_BUF_BYTES;
#pragma unroll
    for (int r = 0; r < 4; r++) {
        int idx = r * 256 + tid;
        int m = idx >> 3;
        int g = idx & 7;
        uint32_t soff = (uint32_t)(m * 128 + ((g ^ (m & 7)) << 4));
        CPA(aDst + soff, g_qext + (size_t)(brow + m) * 512 + cA + g * 8);
        CPA(bDst + soff, g_kext + (size_t)(cb0 + m) * 512 + cB + g * 8);
    }
    CPC();
}

// ---------------- kernel 3: fused mma.sync GEMM + masked-exp epilogue --------
__global__ __launch_bounds__(256, 1) void main_kernel() {
    extern __shared__ char dsm[];
    const uint32_t smb = smem_u32(dsm);
    const int tid  = threadIdx.x;
    const int lane = tid & 31;
    const int wid  = tid >> 5;
    const int wm   = wid >> 2;        // 0..1  (64-row half)
    const int wn   = wid & 3;         // 0..3  (32-col quarter)
    const int band = blockIdx.x >> 1;
    const int ch   = blockIdx.x & 1;
    const int brow = band * BMROW;
    const int cbase = ch * 4096;

    int* advT   = reinterpret_cast<int*>(dsm + SM_ADV);
    float* redA = reinterpret_cast<float*>(dsm + SM_REDA);
    float* redP = reinterpret_cast<float*>(dsm + SM_REDP);

    // ---- per-lane ldmatrix address components ----
    const int matA = lane >> 3;
    const int rowAoff = (lane & 7) + ((matA & 1) << 3);   // row within 16
    const int khA  = matA >> 1;                           // k half (granule +0/+1)
    const int matB = lane >> 3;
    const int nrowOff = ((matB >> 1) << 3) + (lane & 7);
    const int khB  = matB & 1;

    uint32_t aRowByte[4];  int aRowX[4];
#pragma unroll
    for (int mi = 0; mi < 4; mi++) {
        int row = wm * 64 + mi * 16 + rowAoff;
        aRowByte[mi] = (uint32_t)(row * 128);
        aRowX[mi] = row & 7;
    }
    uint32_t bRowByte[2]; int bRowX[2];
#pragma unroll
    for (int nj = 0; nj < 2; nj++) {
        int nrow = wn * 32 + nj * 16 + nrowOff;
        bRowByte[nj] = (uint32_t)(nrow * 128);
        bRowX[nj] = nrow & 7;
    }

    // ---- per-row ad indices (8 rows per lane) ----
    int adiR[4][2];
#pragma unroll
    for (int mi = 0; mi < 4; mi++)
#pragma unroll
        for (int h = 0; h < 2; h++)
            adiR[mi][h] = g_adv[brow + wm * 64 + mi * 16 + h * 8 + (lane >> 2)];

    float sA[4][2], sP[4][2];
#pragma unroll
    for (int mi = 0; mi < 4; mi++)
#pragma unroll
        for (int h = 0; h < 2; h++) { sA[mi][h] = 0.f; sP[mi][h] = 0.f; }

    for (int jt = 0; jt < NTILE; jt++) {
        const int cb0 = cbase + jt * BNCOL;
        __syncthreads();                       // protect advT + smem bufs reuse
        if (tid < BNCOL) advT[tid] = g_adv[cb0 + tid];

        float acc[4][4][4];
#pragma unroll
        for (int mi = 0; mi < 4; mi++)
#pragma unroll
            for (int n8 = 0; n8 < 4; n8++)
#pragma unroll
                for (int r = 0; r < 4; r++) acc[mi][n8][r] = 0.f;

        load_chunk(smb, 0, 0, brow, cb0, tid);

        for (int c = 0; c < NCH; c++) {
            if (c + 1 < NCH) {
                load_chunk(smb, (c + 1) & 1, c + 1, brow, cb0, tid);
                CPW1();
            } else {
                CPW0();
            }
            __syncthreads();
            const uint32_t aB = smb + SM_A0 + (uint32_t)(c & 1) * A_BUF_BYTES;
            const uint32_t bB = smb + SM_B0 + (uint32_t)(c & 1) * A_BUF_BYTES;
#pragma unroll
            for (int s = 0; s < 4; s++) {
                uint32_t af[4][4], bf[2][4];
#pragma unroll
                for (int mi = 0; mi < 4; mi++) {
                    uint32_t gr = (uint32_t)(((s * 2 + khA) ^ aRowX[mi]) << 4);
                    LDSM4(af[mi], aB + aRowByte[mi] + gr);
                }
#pragma unroll
                for (int nj = 0; nj < 2; nj++) {
                    uint32_t gr = (uint32_t)(((s * 2 + khB) ^ bRowX[nj]) << 4);
                    LDSM4(bf[nj], bB + bRowByte[nj] + gr);
                }
#pragma unroll
                for (int mi = 0; mi < 4; mi++)
#pragma unroll
                    for (int n8 = 0; n8 < 4; n8++)
                        MMA16816(acc[mi][n8], af[mi],
                                 bf[n8 >> 1][(n8 & 1) * 2],
                                 bf[n8 >> 1][(n8 & 1) * 2 + 1]);
            }
            __syncthreads();  // all warps done with this buf before overwrite
        }

        // ---- epilogue: exp + masked accumulate ----
#pragma unroll
        for (int n8 = 0; n8 < 4; n8++) {
            int nb = wn * 32 + n8 * 8 + (lane & 3) * 2;
            int a0 = advT[nb], a1 = advT[nb + 1];
#pragma unroll
            for (int mi = 0; mi < 4; mi++)
#pragma unroll
                for (int h = 0; h < 2; h++) {
                    float e0 = fast_exp2(acc[mi][n8][h * 2] * SCALE);
                    float e1 = fast_exp2(acc[mi][n8][h * 2 + 1] * SCALE);
                    if (a0 >= 0) sA[mi][h] += e0;
                    if (a1 >= 0) sA[mi][h] += e1;
                    if (a0 == adiR[mi][h]) sP[mi][h] += e0;
                    if (a1 == adiR[mi][h]) sP[mi][h] += e1;
                }
        }
    }

    // ---- reduce over lane&3 (shfl), then across wn warps (smem) ----
#pragma unroll
    for (int mi = 0; mi < 4; mi++)
#pragma unroll
        for (int h = 0; h < 2; h++) {
#pragma unroll
            for (int o = 1; o < 4; o <<= 1) {
                sA[mi][h] += __shfl_xor_sync(0xffffffffu, sA[mi][h], o);
                sP[mi][h] += __shfl_xor_sync(0xffffffffu, sP[mi][h], o);
            }
        }
    if ((lane & 3) == 0) {
#pragma unroll
        for (int mi = 0; mi < 4; mi++)
#pragma unroll
            for (int h = 0; h < 2; h++) {
                int rl = wm * 64 + mi * 16 + h * 8 + (lane >> 2);
                redA[wn * 128 + rl] = sA[mi][h];
                redP[wn * 128 + rl] = sP[mi][h];
            }
    }
    __syncthreads();
    if (tid < BMROW) {
        float A = redA[tid] + redA[128 + tid] + redA[256 + tid] + redA[384 + tid];
        float P = redP[tid] + redP[128 + tid] + redP[256 + tid] + redP[384 + tid];
        g_rowA[ch * N_ROWS + brow + tid] = A;
        g_rowP[ch * N_ROWS + brow + tid] = P;
    }
}

// ---------------- kernel 4: per-row loss + partial reduce --------------------
__global__ void rowfin_kernel() {
    int r = blockIdx.x * 256 + threadIdx.x;
    float A = g_rowA[r] + g_rowA[N_ROWS + r];
    float P = g_rowP[r] + g_rowP[N_ROWS + r];
    bool valid = g_adv[r] >= 0;
    float l = valid ? (log2f(A) - log2f(P)) * LN2F : 0.f;
    float c = valid ? 1.f : 0.f;
#pragma unroll
    for (int o = 16; o; o >>= 1) {
        l += __shfl_xor_sync(0xffffffffu, l, o);
        c += __shfl_xor_sync(0xffffffffu, c, o);
    }
    __shared__ float wl[8], wc[8];
    int t = threadIdx.x;
    if ((t & 31) == 0) { wl[t >> 5] = l; wc[t >> 5] = c; }
    __syncthreads();
    if (t < 8) {
        float ll = wl[t], cc = wc[t];
#pragma unroll
        for (int o = 4; o; o >>= 1) {
            ll += __shfl_xor_sync(0xffu, ll, o);
            cc += __shfl_xor_sync(0xffu, cc, o);
        }
        if (t == 0) { g_partial[blockIdx.x] = ll; g_pcount[blockIdx.x] = cc; }
    }
}

// ---------------- kernel 5: final --------------------------------------------
__global__ void final_kernel(float* __restrict__ out) {
    int t = threadIdx.x;  // 32
    float s = g_partial[t], c = g_pcount[t];
#pragma unroll
    for (int o = 16; o; o >>= 1) {
        s += __shfl_xor_sync(0xffffffffu, s, o);
        c += __shfl_xor_sync(0xffffffffu, c, o);
    }
    if (t == 0) out[0] = s / fmaxf(c, 1.0f);
}

// ---------------- launch ------------------------------------------------------
extern "C" void kernel_launch(void* const* d_in, const int* in_sizes, int n_in,
                              void* d_out, int out_size) {
    const float* logits = (const float*)d_in[0];
    const float* labels = (const float*)d_in[1];
    const int*   pad    = (const int*)d_in[2];
    const int*   ad     = (const int*)d_in[3];

    cudaFuncSetAttribute(main_kernel, cudaFuncAttributeMaxDynamicSharedMemorySize,
                         DSMEM_BYTES);

    normalize_ext_kernel<<<dim3(N_ROWS, 2), 64>>>(logits, labels);
    adv_kernel<<<N_ROWS / 256, 256>>>(pad, ad);
    main_kernel<<<128, 256, DSMEM_BYTES>>>();
    rowfin_kernel<<<32, 256>>>();
    final_kernel<<<1, 32>>>((float*)d_out);
}

// round 4
// speedup vs baseline: 14.2615x; 2.9655x over previous
#include <cuda_runtime.h>
#include <cuda_fp16.h>
#include <cstdint>
#include <math.h>

#define N_ROWS 8192
#define DIM    256
#define SCALE  28.85390081777927f   /* (1/0.05) * log2(e) */
#define LN2F   0.6931471805599453f

#define BM     128      /* rows per CTA */
#define BN     128      /* cols per tile */
#define KC     64       /* k per chunk */
#define NKC    4        /* chunks per tile (256/64) */
#define NTILE  32       /* col tiles per CTA (4096/128) */
#define NCC    (NTILE * NKC)   /* 128 flattened B chunks */

#define SM_A     0            /* 64 KB: 4 chunks x [128 rows x 128B] */
#define SM_B     65536        /* 4 ring slots x 16 KB */
#define B_SLOT   16384
#define SM_ADV   131072       /* 128 ints */
#define SM_REDA  131584       /* 512 floats */
#define SM_REDP  133632       /* 512 floats */
#define DSMEM_BYTES 135680

// ---------------- device scratch ---------------------------------------------
__device__ __half g_qh[N_ROWS * DIM];
__device__ __half g_kh[N_ROWS * DIM];
__device__ int   g_adv[N_ROWS];
__device__ float g_rowA[2 * N_ROWS];
__device__ float g_rowP[2 * N_ROWS];
__device__ float g_partial[32];
__device__ float g_pcount[32];

// ---------------- PTX helpers ------------------------------------------------
__device__ __forceinline__ uint32_t smem_u32(const void* p) {
    uint32_t a;
    asm("{ .reg .u64 t; cvta.to.shared.u64 t, %1; cvt.u32.u64 %0, t; }" : "=r"(a) : "l"(p));
    return a;
}
__device__ __forceinline__ float fast_exp2(float x) {
    float y; asm("ex2.approx.ftz.f32 %0, %1;" : "=f"(y) : "f"(x)); return y;
}
#define CPA(dst, src) \
    asm volatile("cp.async.cg.shared.global [%0], [%1], 16;" :: "r"(dst), "l"(src) : "memory")
#define CPC()  asm volatile("cp.async.commit_group;" ::: "memory")
#define CPW2() asm volatile("cp.async.wait_group 2;" ::: "memory")
#define CPW1() asm volatile("cp.async.wait_group 1;" ::: "memory")
#define CPW0() asm volatile("cp.async.wait_group 0;" ::: "memory")

#define LDSM4(r, a) \
    asm volatile("ldmatrix.sync.aligned.m8n8.x4.shared.b16 {%0,%1,%2,%3}, [%4];" \
                 : "=r"((r)[0]), "=r"((r)[1]), "=r"((r)[2]), "=r"((r)[3]) : "r"(a))

#define MMA16816(d, a, b0, b1) \
    asm volatile("mma.sync.aligned.m16n8k16.row.col.f32.f16.f16.f32 " \
                 "{%0,%1,%2,%3}, {%4,%5,%6,%7}, {%8,%9}, {%0,%1,%2,%3};" \
                 : "+f"((d)[0]), "+f"((d)[1]), "+f"((d)[2]), "+f"((d)[3]) \
                 : "r"((a)[0]), "r"((a)[1]), "r"((a)[2]), "r"((a)[3]), \
                   "r"(b0), "r"(b1))

// ---------------- kernel 1: normalize -> fp16 --------------------------------
__global__ void normalize_h_kernel(const float* __restrict__ logits,
                                   const float* __restrict__ labels) {
    int row = blockIdx.x;
    const float* src = blockIdx.y ? labels : logits;
    __half* dst = blockIdx.y ? g_kh : g_qh;
    int t = threadIdx.x;  // 64
    float4 v = reinterpret_cast<const float4*>(src + (size_t)row * DIM)[t];
    float ss = v.x * v.x + v.y * v.y + v.z * v.z + v.w * v.w;
#pragma unroll
    for (int o = 16; o; o >>= 1) ss += __shfl_xor_sync(0xffffffffu, ss, o);
    __shared__ float ws[2];
    if ((t & 31) == 0) ws[t >> 5] = ss;
    __syncthreads();
    float inv = 1.0f / fmaxf(sqrtf(ws[0] + ws[1]), 1e-12f);
    __half2 p0 = __floats2half2_rn(v.x * inv, v.y * inv);
    __half2 p1 = __floats2half2_rn(v.z * inv, v.w * inv);
    uint2 pk;
    pk.x = *reinterpret_cast<uint32_t*>(&p0);
    pk.y = *reinterpret_cast<uint32_t*>(&p1);
    *reinterpret_cast<uint2*>(dst + (size_t)row * DIM + 4 * t) = pk;
}

// ---------------- kernel 2: validity/ad --------------------------------------
__global__ void adv_kernel(const int* __restrict__ pad, const int* __restrict__ ad) {
    int i = blockIdx.x * blockDim.x + threadIdx.x;
    if (i < N_ROWS) g_adv[i] = pad[i] ? ad[i] : -1;
}

// ---------------- B chunk issue (cp.async, swizzled) --------------------------
__device__ __forceinline__ void issue_b(uint32_t smb, int cc, int cbase, int tid) {
    const int col0 = cbase + (cc >> 2) * BN;
    const int koff = (cc & 3) * KC;
    uint32_t slot = smb + SM_B + (uint32_t)(cc & 3) * B_SLOT;
#pragma unroll
    for (int r = 0; r < 4; r++) {
        int idx = r * 256 + tid;
        int n = idx >> 3;
        int g = idx & 7;
        uint32_t dst = slot + (uint32_t)(n * 128 + ((g ^ (n & 7)) << 4));
        CPA(dst, g_kh + (size_t)(col0 + n) * DIM + koff + g * 8);
    }
    CPC();
}

// ---------------- kernel 3: fused fp16 mma GEMM + masked-exp epilogue --------
__global__ __launch_bounds__(256, 1) void main_kernel() {
    extern __shared__ char dsm[];
    const uint32_t smb = smem_u32(dsm);
    const int tid  = threadIdx.x;
    const int lane = tid & 31;
    const int wid  = tid >> 5;
    const int wm   = wid >> 2;        // 0..1
    const int wn   = wid & 3;         // 0..3
    const int band = blockIdx.x >> 1;
    const int ch   = blockIdx.x & 1;
    const int brow = band * BM;
    const int cbase = ch * 4096;

    int*   advT = reinterpret_cast<int*>(dsm + SM_ADV);
    float* redA = reinterpret_cast<float*>(dsm + SM_REDA);
    float* redP = reinterpret_cast<float*>(dsm + SM_REDP);

    // ---- ldmatrix lane addressing (identical mapping to R3, verified) ----
    const int matA = lane >> 3;
    const int rowAoff = (lane & 7) + ((matA & 1) << 3);
    const int khA  = matA >> 1;
    const int nrowOff = ((lane >> 4) << 3) + (lane & 7);
    const int khB  = (lane >> 3) & 1;

    uint32_t aRowByte[4]; int aRowX[4];
#pragma unroll
    for (int mi = 0; mi < 4; mi++) {
        int row = wm * 64 + mi * 16 + rowAoff;
        aRowByte[mi] = (uint32_t)(row * 128);
        aRowX[mi] = row & 7;
    }
    uint32_t bRowByte[2]; int bRowX[2];
#pragma unroll
    for (int nj = 0; nj < 2; nj++) {
        int nrow = wn * 32 + nj * 16 + nrowOff;
        bRowByte[nj] = (uint32_t)(nrow * 128);
        bRowX[nj] = nrow & 7;
    }

    int adiR[4][2];
#pragma unroll
    for (int mi = 0; mi < 4; mi++)
#pragma unroll
        for (int h = 0; h < 2; h++)
            adiR[mi][h] = g_adv[brow + wm * 64 + mi * 16 + h * 8 + (lane >> 2)];

    // ---- prologue: A band (64 KB) as cp.async group 0, then B0, B1 ----
#pragma unroll
    for (int r = 0; r < 16; r++) {
        int idx = r * 256 + tid;
        int m = idx >> 5;          // row 0..127
        int g = idx & 31;          // 16B granule 0..31
        uint32_t dst = smb + SM_A + (uint32_t)((g >> 3) * 16384 + m * 128 +
                                               (((g & 7) ^ (m & 7)) << 4));
        CPA(dst, g_qh + (size_t)(brow + m) * DIM + g * 8);
    }
    CPC();
    issue_b(smb, 0, cbase, tid);
    issue_b(smb, 1, cbase, tid);

    float sA[4][2], sP[4][2];
#pragma unroll
    for (int mi = 0; mi < 4; mi++)
#pragma unroll
        for (int h = 0; h < 2; h++) { sA[mi][h] = 0.f; sP[mi][h] = 0.f; }

    for (int jt = 0; jt < NTILE; jt++) {
        float acc[4][4][4];
#pragma unroll
        for (int mi = 0; mi < 4; mi++)
#pragma unroll
            for (int n8 = 0; n8 < 4; n8++)
#pragma unroll
                for (int r = 0; r < 4; r++) acc[mi][n8][r] = 0.f;

#pragma unroll
        for (int kc = 0; kc < NKC; kc++) {
            const int cc = jt * NKC + kc;
            if (cc + 2 < NCC) { issue_b(smb, cc + 2, cbase, tid); CPW2(); }
            else if (cc + 2 == NCC) { CPW1(); }
            else { CPW0(); }
            __syncthreads();
            if (kc == 0 && tid < BN) advT[tid] = g_adv[cbase + jt * BN + tid];

            const uint32_t aC = smb + SM_A + (uint32_t)kc * 16384;
            const uint32_t bB = smb + SM_B + (uint32_t)(cc & 3) * B_SLOT;
#pragma unroll
            for (int s = 0; s < 4; s++) {
                uint32_t af[4][4], bf[2][4];
#pragma unroll
                for (int mi = 0; mi < 4; mi++) {
                    uint32_t gr = (uint32_t)(((s * 2 + khA) ^ aRowX[mi]) << 4);
                    LDSM4(af[mi], aC + aRowByte[mi] + gr);
                }
#pragma unroll
                for (int nj = 0; nj < 2; nj++) {
                    uint32_t gr = (uint32_t)(((s * 2 + khB) ^ bRowX[nj]) << 4);
                    LDSM4(bf[nj], bB + bRowByte[nj] + gr);
                }
#pragma unroll
                for (int mi = 0; mi < 4; mi++)
#pragma unroll
                    for (int n8 = 0; n8 < 4; n8++)
                        MMA16816(acc[mi][n8], af[mi],
                                 bf[n8 >> 1][(n8 & 1) * 2],
                                 bf[n8 >> 1][(n8 & 1) * 2 + 1]);
            }
        }

        // ---- epilogue: exp + masked accumulate ----
#pragma unroll
        for (int n8 = 0; n8 < 4; n8++) {
            int nb = wn * 32 + n8 * 8 + (lane & 3) * 2;
            int a0 = advT[nb], a1 = advT[nb + 1];
#pragma unroll
            for (int mi = 0; mi < 4; mi++)
#pragma unroll
                for (int h = 0; h < 2; h++) {
                    float e0 = fast_exp2(acc[mi][n8][h * 2] * SCALE);
                    float e1 = fast_exp2(acc[mi][n8][h * 2 + 1] * SCALE);
                    if (a0 >= 0) sA[mi][h] += e0;
                    if (a1 >= 0) sA[mi][h] += e1;
                    if (a0 == adiR[mi][h]) sP[mi][h] += e0;
                    if (a1 == adiR[mi][h]) sP[mi][h] += e1;
                }
        }
    }

    // ---- reduce over lane&3, then across wn warps via smem ----
#pragma unroll
    for (int mi = 0; mi < 4; mi++)
#pragma unroll
        for (int h = 0; h < 2; h++) {
#pragma unroll
            for (int o = 1; o < 4; o <<= 1) {
                sA[mi][h] += __shfl_xor_sync(0xffffffffu, sA[mi][h], o);
                sP[mi][h] += __shfl_xor_sync(0xffffffffu, sP[mi][h], o);
            }
        }
    if ((lane & 3) == 0) {
#pragma unroll
        for (int mi = 0; mi < 4; mi++)
#pragma unroll
            for (int h = 0; h < 2; h++) {
                int rl = wm * 64 + mi * 16 + h * 8 + (lane >> 2);
                redA[wn * 128 + rl] = sA[mi][h];
                redP[wn * 128 + rl] = sP[mi][h];
            }
    }
    __syncthreads();
    if (tid < BM) {
        float A = redA[tid] + redA[128 + tid] + redA[256 + tid] + redA[384 + tid];
        float P = redP[tid] + redP[128 + tid] + redP[256 + tid] + redP[384 + tid];
        g_rowA[ch * N_ROWS + brow + tid] = A;
        g_rowP[ch * N_ROWS + brow + tid] = P;
    }
}

// ---------------- kernel 4: per-row loss + partial reduce --------------------
__global__ void rowfin_kernel() {
    int r = blockIdx.x * 256 + threadIdx.x;
    float A = g_rowA[r] + g_rowA[N_ROWS + r];
    float P = g_rowP[r] + g_rowP[N_ROWS + r];
    bool valid = g_adv[r] >= 0;
    float l = valid ? (log2f(A) - log2f(P)) * LN2F : 0.f;
    float c = valid ? 1.f : 0.f;
#pragma unroll
    for (int o = 16; o; o >>= 1) {
        l += __shfl_xor_sync(0xffffffffu, l, o);
        c += __shfl_xor_sync(0xffffffffu, c, o);
    }
    __shared__ float wl[8], wc[8];
    int t = threadIdx.x;
    if ((t & 31) == 0) { wl[t >> 5] = l; wc[t >> 5] = c; }
    __syncthreads();
    if (t < 8) {
        float ll = wl[t], cc = wc[t];
#pragma unroll
        for (int o = 4; o; o >>= 1) {
            ll += __shfl_xor_sync(0xffu, ll, o);
            cc += __shfl_xor_sync(0xffu, cc, o);
        }
        if (t == 0) { g_partial[blockIdx.x] = ll; g_pcount[blockIdx.x] = cc; }
    }
}

// ---------------- kernel 5: final --------------------------------------------
__global__ void final_kernel(float* __restrict__ out) {
    int t = threadIdx.x;  // 32
    float s = g_partial[t], c = g_pcount[t];
#pragma unroll
    for (int o = 16; o; o >>= 1) {
        s += __shfl_xor_sync(0xffffffffu, s, o);
        c += __shfl_xor_sync(0xffffffffu, c, o);
    }
    if (t == 0) out[0] = s / fmaxf(c, 1.0f);
}

// ---------------- launch ------------------------------------------------------
extern "C" void kernel_launch(void* const* d_in, const int* in_sizes, int n_in,
                              void* d_out, int out_size) {
    const float* logits = (const float*)d_in[0];
    const float* labels = (const float*)d_in[1];
    const int*   pad    = (const int*)d_in[2];
    const int*   ad     = (const int*)d_in[3];

    cudaFuncSetAttribute(main_kernel, cudaFuncAttributeMaxDynamicSharedMemorySize,
                         DSMEM_BYTES);

    normalize_h_kernel<<<dim3(N_ROWS, 2), 64>>>(logits, labels);
    adv_kernel<<<N_ROWS / 256, 256>>>(pad, ad);
    main_kernel<<<128, 256, DSMEM_BYTES>>>();
    rowfin_kernel<<<32, 256>>>();
    final_kernel<<<1, 32>>>((float*)d_out);
}

// round 6
// speedup vs baseline: 15.5984x; 1.0937x over previous
#include <cuda_runtime.h>
#include <cuda_fp16.h>
#include <cstdint>
#include <math.h>

#define N_ROWS 8192
#define DIM    256
#define SCALE  28.85390081777927f   /* (1/0.05) * log2(e) */
#define LN2F   0.6931471805599453f

#define BM     128
#define BN     128
#define KC     64
#define NKC    4
#define NTILE  32
#define NCC    (NTILE * NKC)

#define SM_A     0            /* 64 KB: 4 k-chunks x [128 rows x 128B] */
#define SM_B     65536        /* 4 ring slots x 16 KB */
#define B_SLOT   16384
#define SM_ADV   131072       /* 2 x 128 ints */
#define SM_REDA  132096
#define SM_REDP  134144
#define DSMEM_BYTES 136192

// ---------------- device scratch ---------------------------------------------
__device__ __half g_qh[N_ROWS * DIM];     // q scaled by SCALE
__device__ __half g_kh[N_ROWS * DIM];
__device__ int   g_adv[N_ROWS];
__device__ float g_rowA[2 * N_ROWS];
__device__ float g_rowP[2 * N_ROWS];

// ---------------- PTX helpers ------------------------------------------------
__device__ __forceinline__ uint32_t smem_u32(const void* p) {
    uint32_t a;
    asm("{ .reg .u64 t; cvta.to.shared.u64 t, %1; cvt.u32.u64 %0, t; }" : "=r"(a) : "l"(p));
    return a;
}
__device__ __forceinline__ float fast_exp2(float x) {
    float y; asm("ex2.approx.ftz.f32 %0, %1;" : "=f"(y) : "f"(x)); return y;
}
#define CPA(dst, src) \
    asm volatile("cp.async.cg.shared.global [%0], [%1], 16;" :: "r"(dst), "l"(src) : "memory")
#define CPC()  asm volatile("cp.async.commit_group;" ::: "memory")
#define CPW2() asm volatile("cp.async.wait_group 2;" ::: "memory")
#define CPW1() asm volatile("cp.async.wait_group 1;" ::: "memory")
#define CPW0() asm volatile("cp.async.wait_group 0;" ::: "memory")

#define LDSM4(r, a) \
    asm volatile("ldmatrix.sync.aligned.m8n8.x4.shared.b16 {%0,%1,%2,%3}, [%4];" \
                 : "=r"((r)[0]), "=r"((r)[1]), "=r"((r)[2]), "=r"((r)[3]) : "r"(a))

#define MMA16816(d, a, b0, b1) \
    asm volatile("mma.sync.aligned.m16n8k16.row.col.f32.f16.f16.f32 " \
                 "{%0,%1,%2,%3}, {%4,%5,%6,%7}, {%8,%9}, {%0,%1,%2,%3};" \
                 : "+f"((d)[0]), "+f"((d)[1]), "+f"((d)[2]), "+f"((d)[3]) \
                 : "r"((a)[0]), "r"((a)[1]), "r"((a)[2]), "r"((a)[3]), \
                   "r"(b0), "r"(b1))

// ---------------- kernel 1: normalize (+adv) -> fp16 -------------------------
__global__ void normalize_h_kernel(const float* __restrict__ logits,
                                   const float* __restrict__ labels,
                                   const int* __restrict__ pad,
                                   const int* __restrict__ ad) {
    const int lane = threadIdx.x & 31;
    const int warp = threadIdx.x >> 5;
    const int row  = blockIdx.x * 8 + warp;
    const float* src = blockIdx.y ? labels : logits;
    __half* dst = blockIdx.y ? g_kh : g_qh;
    const float post = blockIdx.y ? 1.0f : SCALE;   // fold exp scale into q
    const float* rp = src + (size_t)row * DIM + lane * 8;
    float4 v0 = *reinterpret_cast<const float4*>(rp);
    float4 v1 = *reinterpret_cast<const float4*>(rp + 4);
    float ss = v0.x*v0.x + v0.y*v0.y + v0.z*v0.z + v0.w*v0.w
             + v1.x*v1.x + v1.y*v1.y + v1.z*v1.z + v1.w*v1.w;
#pragma unroll
    for (int o = 16; o; o >>= 1) ss += __shfl_xor_sync(0xffffffffu, ss, o);
    float s = (1.0f / fmaxf(sqrtf(ss), 1e-12f)) * post;
    __half2 h0 = __floats2half2_rn(v0.x * s, v0.y * s);
    __half2 h1 = __floats2half2_rn(v0.z * s, v0.w * s);
    __half2 h2 = __floats2half2_rn(v1.x * s, v1.y * s);
    __half2 h3 = __floats2half2_rn(v1.z * s, v1.w * s);
    uint4 pk;
    pk.x = *reinterpret_cast<uint32_t*>(&h0);
    pk.y = *reinterpret_cast<uint32_t*>(&h1);
    pk.z = *reinterpret_cast<uint32_t*>(&h2);
    pk.w = *reinterpret_cast<uint32_t*>(&h3);
    *reinterpret_cast<uint4*>(dst + (size_t)row * DIM + lane * 8) = pk;
    if (blockIdx.y == 0 && lane == 0)
        g_adv[row] = pad[row] ? ad[row] : -1;
}

// ---------------- B chunk issue (cp.async, swizzled) --------------------------
__device__ __forceinline__ void issue_b(uint32_t smb, int cc, int cbase, int tid) {
    const int col0 = cbase + (cc >> 2) * BN;
    const int koff = (cc & 3) * KC;
    uint32_t slot = smb + SM_B + (uint32_t)(cc & 3) * B_SLOT;
#pragma unroll
    for (int r = 0; r < 4; r++) {
        int idx = r * 256 + tid;
        int n = idx >> 3;
        int g = idx & 7;
        uint32_t dst = slot + (uint32_t)(n * 128 + ((g ^ (n & 7)) << 4));
        CPA(dst, g_kh + (size_t)(col0 + n) * DIM + koff + g * 8);
    }
    CPC();
}

// ---------------- one tile: MMA into accC, epilogue of accP interleaved ------
template <bool DO_EPI>
__device__ __forceinline__ void tile_step(
    int jt, float (&accC)[4][4][4], float (&accP)[4][4][4],
    uint32_t smb, int cbase, int tid, int lane, int wn,
    const uint32_t (&aRowByte)[4], const int (&aRowX)[4],
    const uint32_t (&bRowByte)[2], const int (&bRowX)[2],
    int khA, int khB, const int (&adiR)[4][2],
    float (&sA)[4][2], float (&sP)[4][2], int* advT)
{
#pragma unroll
    for (int mi = 0; mi < 4; mi++)
#pragma unroll
        for (int n8 = 0; n8 < 4; n8++)
#pragma unroll
            for (int r = 0; r < 4; r++) accC[mi][n8][r] = 0.f;

#pragma unroll
    for (int kc = 0; kc < NKC; kc++) {
        const int cc = jt * NKC + kc;
        if (cc + 2 < NCC) { issue_b(smb, cc + 2, cbase, tid); CPW2(); }
        else if (cc + 2 == NCC) { CPW1(); }
        else { CPW0(); }
        __syncthreads();
        if (kc == 0 && tid < BN) advT[(jt & 1) * BN + tid] = g_adv[cbase + jt * BN + tid];

        const uint32_t aC = smb + SM_A + (uint32_t)kc * 16384;
        const uint32_t bB = smb + SM_B + (uint32_t)(cc & 3) * B_SLOT;
#pragma unroll
        for (int s = 0; s < 4; s++) {
            uint32_t af[4][4], bf[2][4];
#pragma unroll
            for (int mi = 0; mi < 4; mi++) {
                uint32_t gr = (uint32_t)(((s * 2 + khA) ^ aRowX[mi]) << 4);
                LDSM4(af[mi], aC + aRowByte[mi] + gr);
            }
#pragma unroll
            for (int nj = 0; nj < 2; nj++) {
                uint32_t gr = (uint32_t)(((s * 2 + khB) ^ bRowX[nj]) << 4);
                LDSM4(bf[nj], bB + bRowByte[nj] + gr);
            }
#pragma unroll
            for (int mi = 0; mi < 4; mi++)
#pragma unroll
                for (int n8 = 0; n8 < 4; n8++)
                    MMA16816(accC[mi][n8], af[mi],
                             bf[n8 >> 1][(n8 & 1) * 2],
                             bf[n8 >> 1][(n8 & 1) * 2 + 1]);
        }

        if (DO_EPI) {   // previous tile's epilogue, column group n8 == kc
            const int pb = ((jt + 1) & 1) * BN;
            const int nb = wn * 32 + kc * 8 + (lane & 3) * 2;
            const int a0 = advT[pb + nb], a1 = advT[pb + nb + 1];
#pragma unroll
            for (int mi = 0; mi < 4; mi++)
#pragma unroll
                for (int h = 0; h < 2; h++) {
                    float e0 = fast_exp2(accP[mi][kc][h * 2]);
                    float e1 = fast_exp2(accP[mi][kc][h * 2 + 1]);
                    if (a0 >= 0) sA[mi][h] += e0;
                    if (a1 >= 0) sA[mi][h] += e1;
                    if (a0 == adiR[mi][h]) sP[mi][h] += e0;
                    if (a1 == adiR[mi][h]) sP[mi][h] += e1;
                }
        }
    }
}

// ---------------- kernel 2: fused fp16 mma GEMM + hidden epilogue ------------
__global__ __launch_bounds__(256, 1) void main_kernel() {
    extern __shared__ char dsm[];
    const uint32_t smb = smem_u32(dsm);
    const int tid  = threadIdx.x;
    const int lane = tid & 31;
    const int wid  = tid >> 5;
    const int wm   = wid >> 2;
    const int wn   = wid & 3;
    const int band = blockIdx.x >> 1;
    const int ch   = blockIdx.x & 1;
    const int brow = band * BM;
    const int cbase = ch * 4096;

    int*   advT = reinterpret_cast<int*>(dsm + SM_ADV);
    float* redA = reinterpret_cast<float*>(dsm + SM_REDA);
    float* redP = reinterpret_cast<float*>(dsm + SM_REDP);

    const int matA = lane >> 3;
    const int rowAoff = (lane & 7) + ((matA & 1) << 3);
    const int khA  = matA >> 1;
    const int nrowOff = ((lane >> 4) << 3) + (lane & 7);
    const int khB  = (lane >> 3) & 1;

    uint32_t aRowByte[4]; int aRowX[4];
#pragma unroll
    for (int mi = 0; mi < 4; mi++) {
        int row = wm * 64 + mi * 16 + rowAoff;
        aRowByte[mi] = (uint32_t)(row * 128);
        aRowX[mi] = row & 7;
    }
    uint32_t bRowByte[2]; int bRowX[2];
#pragma unroll
    for (int nj = 0; nj < 2; nj++) {
        int nrow = wn * 32 + nj * 16 + nrowOff;
        bRowByte[nj] = (uint32_t)(nrow * 128);
        bRowX[nj] = nrow & 7;
    }

    int adiR[4][2];
#pragma unroll
    for (int mi = 0; mi < 4; mi++)
#pragma unroll
        for (int h = 0; h < 2; h++)
            adiR[mi][h] = g_adv[brow + wm * 64 + mi * 16 + h * 8 + (lane >> 2)];

    // ---- prologue: A band (64 KB), then B0, B1 ----
#pragma unroll
    for (int r = 0; r < 16; r++) {
        int idx = r * 256 + tid;
        int m = idx >> 5;
        int g = idx & 31;
        uint32_t dst = smb + SM_A + (uint32_t)((g >> 3) * 16384 + m * 128 +
                                               (((g & 7) ^ (m & 7)) << 4));
        CPA(dst, g_qh + (size_t)(brow + m) * DIM + g * 8);
    }
    CPC();
    issue_b(smb, 0, cbase, tid);
    issue_b(smb, 1, cbase, tid);

    float sA[4][2], sP[4][2];
#pragma unroll
    for (int mi = 0; mi < 4; mi++)
#pragma unroll
        for (int h = 0; h < 2; h++) { sA[mi][h] = 0.f; sP[mi][h] = 0.f; }

    float acc0[4][4][4], acc1[4][4][4];

    tile_step<false>(0, acc0, acc1, smb, cbase, tid, lane, wn,
                     aRowByte, aRowX, bRowByte, bRowX, khA, khB, adiR, sA, sP, advT);
#pragma unroll 1
    for (int j2 = 0; j2 < 15; j2++) {
        const int jt = 1 + j2 * 2;
        tile_step<true>(jt, acc1, acc0, smb, cbase, tid, lane, wn,
                        aRowByte, aRowX, bRowByte, bRowX, khA, khB, adiR, sA, sP, advT);
        tile_step<true>(jt + 1, acc0, acc1, smb, cbase, tid, lane, wn,
                        aRowByte, aRowX, bRowByte, bRowX, khA, khB, adiR, sA, sP, advT);
    }
    tile_step<true>(31, acc1, acc0, smb, cbase, tid, lane, wn,
                    aRowByte, aRowX, bRowByte, bRowX, khA, khB, adiR, sA, sP, advT);

    // ---- trailing epilogue for tile 31 (buffer acc1, adv buf 1) ----
#pragma unroll
    for (int n8 = 0; n8 < 4; n8++) {
        const int nb = wn * 32 + n8 * 8 + (lane & 3) * 2;
        const int a0 = advT[BN + nb], a1 = advT[BN + nb + 1];
#pragma unroll
        for (int mi = 0; mi < 4; mi++)
#pragma unroll
            for (int h = 0; h < 2; h++) {
                float e0 = fast_exp2(acc1[mi][n8][h * 2]);
                float e1 = fast_exp2(acc1[mi][n8][h * 2 + 1]);
                if (a0 >= 0) sA[mi][h] += e0;
                if (a1 >= 0) sA[mi][h] += e1;
                if (a0 == adiR[mi][h]) sP[mi][h] += e0;
                if (a1 == adiR[mi][h]) sP[mi][h] += e1;
            }
    }

    // ---- reduce over lane&3, then across wn warps ----
#pragma unroll
    for (int mi = 0; mi < 4; mi++)
#pragma unroll
        for (int h = 0; h < 2; h++) {
#pragma unroll
            for (int o = 1; o < 4; o <<= 1) {
                sA[mi][h] += __shfl_xor_sync(0xffffffffu, sA[mi][h], o);
                sP[mi][h] += __shfl_xor_sync(0xffffffffu, sP[mi][h], o);
            }
        }
    if ((lane & 3) == 0) {
#pragma unroll
        for (int mi = 0; mi < 4; mi++)
#pragma unroll
            for (int h = 0; h < 2; h++) {
                int rl = wm * 64 + mi * 16 + h * 8 + (lane >> 2);
                redA[wn * 128 + rl] = sA[mi][h];
                redP[wn * 128 + rl] = sP[mi][h];
            }
    }
    __syncthreads();
    if (tid < BM) {
        float A = redA[tid] + redA[128 + tid] + redA[256 + tid] + redA[384 + tid];
        float P = redP[tid] + redP[128 + tid] + redP[256 + tid] + redP[384 + tid];
        g_rowA[ch * N_ROWS + brow + tid] = A;
        g_rowP[ch * N_ROWS + brow + tid] = P;
    }
}

// ---------------- kernel 3: finalize (merged rowfin + final) -----------------
__global__ void finalize_kernel(float* __restrict__ out) {
    const int t = threadIdx.x;   // 1024
    float l = 0.f, c = 0.f;
#pragma unroll
    for (int i = 0; i < 8; i++) {
        int r = i * 1024 + t;
        float A = g_rowA[r] + g_rowA[N_ROWS + r];
        float P = g_rowP[r] + g_rowP[N_ROWS + r];
        if (g_adv[r] >= 0) {
            l += (log2f(A) - log2f(P)) * LN2F;
            c += 1.f;
        }
    }
#pragma unroll
    for (int o = 16; o; o >>= 1) {
        l += __shfl_xor_sync(0xffffffffu, l, o);
        c += __shfl_xor_sync(0xffffffffu, c, o);
    }
    __shared__ float sl[32], sc[32];
    if ((t & 31) == 0) { sl[t >> 5] = l; sc[t >> 5] = c; }
    __syncthreads();
    if (t < 32) {
        l = sl[t]; c = sc[t];
#pragma unroll
        for (int o = 16; o; o >>= 1) {
            l += __shfl_xor_sync(0xffffffffu, l, o);
            c += __shfl_xor_sync(0xffffffffu, c, o);
        }
        if (t == 0) out[0] = l / fmaxf(c, 1.0f);
    }
}

// ---------------- launch ------------------------------------------------------
extern "C" void kernel_launch(void* const* d_in, const int* in_sizes, int n_in,
                              void* d_out, int out_size) {
    const float* logits = (const float*)d_in[0];
    const float* labels = (const float*)d_in[1];
    const int*   pad    = (const int*)d_in[2];
    const int*   ad     = (const int*)d_in[3];

    cudaFuncSetAttribute(main_kernel, cudaFuncAttributeMaxDynamicSharedMemorySize,
                         DSMEM_BYTES);

    normalize_h_kernel<<<dim3(1024, 2), 256>>>(logits, labels, pad, ad);
    main_kernel<<<128, 256, DSMEM_BYTES>>>();
    finalize_kernel<<<1, 1024>>>((float*)d_out);
}

// round 8
// speedup vs baseline: 21.2151x; 1.3601x over previous
#include <cuda_runtime.h>
#include <cuda_fp16.h>
#include <cstdint>
#include <math.h>

#define N_ROWS 8192
#define DIM    256
#define CPAD   8320                 /* compacted capacity: 8192 + 128 pad */
#define SCALE  28.85390081777927f   /* (1/0.05) * log2(e) */
#define LN2F   0.6931471805599453f

#define BM     64       /* rows per CTA band (compacted) */
#define BN     128      /* cols per tile (compacted) */
#define KC     64

#define SM_A     0            /* 32 KB: 4 k-chunks x [64 rows x 128B] */
#define SM_B     32768        /* 4 ring slots x 16 KB */
#define B_SLOT   16384
#define SM_ADV   98304        /* 128 ints */
#define SM_REDA  98816        /* 256 floats */
#define SM_REDP  99840        /* 256 floats */
#define DSMEM_BYTES 100864

// ---------------- device scratch ---------------------------------------------
__device__ __half g_qc[CPAD * DIM];     // compacted, q scaled by SCALE
__device__ __half g_kc[CPAD * DIM];     // compacted
__device__ int   g_cadv[CPAD];          // compacted ad (valid rows), -1 in pad
__device__ int   g_cidx[N_ROWS];        // exclusive prefix of validity
__device__ int   g_cnt;                 // number of valid rows
__device__ float g_rowA[2 * CPAD];
__device__ float g_rowP[2 * CPAD];

// ---------------- PTX helpers ------------------------------------------------
__device__ __forceinline__ uint32_t smem_u32(const void* p) {
    uint32_t a;
    asm("{ .reg .u64 t; cvta.to.shared.u64 t, %1; cvt.u32.u64 %0, t; }" : "=r"(a) : "l"(p));
    return a;
}
__device__ __forceinline__ float fast_exp2(float x) {
    float y; asm("ex2.approx.ftz.f32 %0, %1;" : "=f"(y) : "f"(x)); return y;
}
#define CPA(dst, src) \
    asm volatile("cp.async.cg.shared.global [%0], [%1], 16;" :: "r"(dst), "l"(src) : "memory")
#define CPC()  asm volatile("cp.async.commit_group;" ::: "memory")
#define CPW2() asm volatile("cp.async.wait_group 2;" ::: "memory")
#define CPW1() asm volatile("cp.async.wait_group 1;" ::: "memory")
#define CPW0() asm volatile("cp.async.wait_group 0;" ::: "memory")

#define LDSM4(r, a) \
    asm volatile("ldmatrix.sync.aligned.m8n8.x4.shared.b16 {%0,%1,%2,%3}, [%4];" \
                 : "=r"((r)[0]), "=r"((r)[1]), "=r"((r)[2]), "=r"((r)[3]) : "r"(a))

#define MMA16816(d, a, b0, b1) \
    asm volatile("mma.sync.aligned.m16n8k16.row.col.f32.f16.f16.f32 " \
                 "{%0,%1,%2,%3}, {%4,%5,%6,%7}, {%8,%9}, {%0,%1,%2,%3};" \
                 : "+f"((d)[0]), "+f"((d)[1]), "+f"((d)[2]), "+f"((d)[3]) \
                 : "r"((a)[0]), "r"((a)[1]), "r"((a)[2]), "r"((a)[3]), \
                   "r"(b0), "r"(b1))

// ---------------- kernel 1: validity scan ------------------------------------
__global__ void scan_kernel(const int* __restrict__ pad) {
    const int t = threadIdx.x;        // 1024
    const int lane = t & 31, warp = t >> 5;
    int4 a = reinterpret_cast<const int4*>(pad)[2 * t];
    int4 b = reinterpret_cast<const int4*>(pad)[2 * t + 1];
    int v[8] = {a.x ? 1 : 0, a.y ? 1 : 0, a.z ? 1 : 0, a.w ? 1 : 0,
                b.x ? 1 : 0, b.y ? 1 : 0, b.z ? 1 : 0, b.w ? 1 : 0};
    int pre[8], s = 0;
#pragma unroll
    for (int i = 0; i < 8; i++) { pre[i] = s; s += v[i]; }
    int incl = s;
#pragma unroll
    for (int o = 1; o < 32; o <<= 1) {
        int n = __shfl_up_sync(0xffffffffu, incl, o);
        if (lane >= o) incl += n;
    }
    __shared__ int wtot[32], woff[32];
    if (lane == 31) wtot[warp] = incl;
    __syncthreads();
    if (t < 32) {
        int w = wtot[t], wi = w;
#pragma unroll
        for (int o = 1; o < 32; o <<= 1) {
            int n = __shfl_up_sync(0xffffffffu, wi, o);
            if (t >= o) wi += n;
        }
        woff[t] = wi - w;
        if (t == 31) g_cnt = wi;
    }
    __syncthreads();
    int base = woff[warp] + incl - s;
#pragma unroll
    for (int i = 0; i < 8; i++) g_cidx[8 * t + i] = base + pre[i];
}

// ---------------- kernel 2: normalize + scatter-compact ----------------------
__global__ void scatter_kernel(const float* __restrict__ logits,
                               const float* __restrict__ labels,
                               const int* __restrict__ pad,
                               const int* __restrict__ ad) {
    const int lane = threadIdx.x & 31;
    const int warp = threadIdx.x >> 5;
    const int row  = blockIdx.x * 8 + warp;
    if (!pad[row]) return;
    const int j = g_cidx[row];
    const float* src = blockIdx.y ? labels : logits;
    __half* dst = blockIdx.y ? g_kc : g_qc;
    const float post = blockIdx.y ? 1.0f : SCALE;
    const float* rp = src + (size_t)row * DIM + lane * 8;
    float4 v0 = *reinterpret_cast<const float4*>(rp);
    float4 v1 = *reinterpret_cast<const float4*>(rp + 4);
    float ss = v0.x*v0.x + v0.y*v0.y + v0.z*v0.z + v0.w*v0.w
             + v1.x*v1.x + v1.y*v1.y + v1.z*v1.z + v1.w*v1.w;
#pragma unroll
    for (int o = 16; o; o >>= 1) ss += __shfl_xor_sync(0xffffffffu, ss, o);
    float s = (1.0f / fmaxf(sqrtf(ss), 1e-12f)) * post;
    __half2 h0 = __floats2half2_rn(v0.x * s, v0.y * s);
    __half2 h1 = __floats2half2_rn(v0.z * s, v0.w * s);
    __half2 h2 = __floats2half2_rn(v1.x * s, v1.y * s);
    __half2 h3 = __floats2half2_rn(v1.z * s, v1.w * s);
    uint4 pk;
    pk.x = *reinterpret_cast<uint32_t*>(&h0);
    pk.y = *reinterpret_cast<uint32_t*>(&h1);
    pk.z = *reinterpret_cast<uint32_t*>(&h2);
    pk.w = *reinterpret_cast<uint32_t*>(&h3);
    *reinterpret_cast<uint4*>(dst + (size_t)j * DIM + lane * 8) = pk;
    if (blockIdx.y == 0 && lane == 0) g_cadv[j] = ad[row];
}

// ---------------- kernel 3: zero-pad compacted tail --------------------------
__global__ void pad_kernel() {
    const int cnt = g_cnt;
    const int t = threadIdx.x;   // 256
    const uint4 z = {0u, 0u, 0u, 0u};
#pragma unroll
    for (int i = 0; i < 16; i++) {
        int idx = i * 256 + t;              // 4096 uint4 = 128 rows
        int row = cnt + (idx >> 5);
        int g = idx & 31;
        reinterpret_cast<uint4*>(g_qc + (size_t)row * DIM)[g] = z;
        reinterpret_cast<uint4*>(g_kc + (size_t)row * DIM)[g] = z;
    }
    if (t < 128) g_cadv[cnt + t] = -1;
}

// ---------------- B chunk issue (cp.async, swizzled) --------------------------
__device__ __forceinline__ void issue_b(uint32_t smb, int l, int ch, int tid) {
    const int tile = ch + ((l >> 2) << 1);
    const int col0 = tile * BN;
    const int koff = (l & 3) * KC;
    uint32_t slot = smb + SM_B + (uint32_t)(l & 3) * B_SLOT;
#pragma unroll
    for (int r = 0; r < 4; r++) {
        int idx = r * 256 + tid;
        int n = idx >> 3;
        int g = idx & 7;
        uint32_t dst = slot + (uint32_t)(n * 128 + ((g ^ (n & 7)) << 4));
        CPA(dst, g_kc + (size_t)(col0 + n) * DIM + koff + g * 8);
    }
    CPC();
}

// ---------------- kernel 4: fused compacted GEMM + masked-exp ----------------
__global__ __launch_bounds__(256, 2) void main_kernel() {
    extern __shared__ char dsm[];
    const uint32_t smb = smem_u32(dsm);
    const int tid  = threadIdx.x;
    const int lane = tid & 31;
    const int wid  = tid >> 5;
    const int wm   = wid >> 2;        // 0..1 (32-row half of 64)
    const int wn   = wid & 3;         // 0..3 (32-col quarter of 128)
    const int band = blockIdx.x >> 1;
    const int ch   = blockIdx.x & 1;
    const int brow = band * BM;
    const int cnt  = g_cnt;
    if (brow >= cnt) return;
    const int T   = (cnt + 127) >> 7;
    const int myT = (T - ch + 1) >> 1;
    if (myT == 0) {
        if (tid < BM) {
            g_rowA[ch * CPAD + brow + tid] = 0.f;
            g_rowP[ch * CPAD + brow + tid] = 0.f;
        }
        return;
    }
    const int NC = 4 * myT;

    int*   advT = reinterpret_cast<int*>(dsm + SM_ADV);
    float* redA = reinterpret_cast<float*>(dsm + SM_REDA);
    float* redP = reinterpret_cast<float*>(dsm + SM_REDP);

    const int matA = lane >> 3;
    const int rowAoff = (lane & 7) + ((matA & 1) << 3);
    const int khA  = matA >> 1;
    const int nrowOff = ((lane >> 4) << 3) + (lane & 7);
    const int khB  = (lane >> 3) & 1;

    uint32_t aRowByte[2]; int aRowX[2];
#pragma unroll
    for (int mi = 0; mi < 2; mi++) {
        int row = wm * 32 + mi * 16 + rowAoff;
        aRowByte[mi] = (uint32_t)(row * 128);
        aRowX[mi] = row & 7;
    }
    uint32_t bRowByte[2]; int bRowX[2];
#pragma unroll
    for (int nj = 0; nj < 2; nj++) {
        int nrow = wn * 32 + nj * 16 + nrowOff;
        bRowByte[nj] = (uint32_t)(nrow * 128);
        bRowX[nj] = nrow & 7;
    }

    int adiR[2][2];
#pragma unroll
    for (int mi = 0; mi < 2; mi++)
#pragma unroll
        for (int h = 0; h < 2; h++)
            adiR[mi][h] = g_cadv[brow + wm * 32 + mi * 16 + h * 8 + (lane >> 2)];

    // ---- prologue: A band (32 KB), then B chunks 0,1 ----
#pragma unroll
    for (int r = 0; r < 8; r++) {
        int idx = r * 256 + tid;
        int m = idx >> 5;          // row 0..63
        int g = idx & 31;          // 16B granule
        uint32_t dst = smb + SM_A + (uint32_t)((g >> 3) * 8192 + m * 128 +
                                               (((g & 7) ^ (m & 7)) << 4));
        CPA(dst, g_qc + (size_t)(brow + m) * DIM + g * 8);
    }
    CPC();
    issue_b(smb, 0, ch, tid);
    if (NC > 1) issue_b(smb, 1, ch, tid);
    else CPC();   // keep group count consistent

    float sA[2][2], sP[2][2];
#pragma unroll
    for (int mi = 0; mi < 2; mi++)
#pragma unroll
        for (int h = 0; h < 2; h++) { sA[mi][h] = 0.f; sP[mi][h] = 0.f; }

#pragma unroll 1
    for (int tloc = 0; tloc < myT; tloc++) {
        float acc[2][4][4];
#pragma unroll
        for (int mi = 0; mi < 2; mi++)
#pragma unroll
            for (int n8 = 0; n8 < 4; n8++)
#pragma unroll
                for (int r = 0; r < 4; r++) acc[mi][n8][r] = 0.f;

#pragma unroll
        for (int kc = 0; kc < 4; kc++) {
            const int l = tloc * 4 + kc;
            if (l + 2 < NC) { issue_b(smb, l + 2, ch, tid); CPW2(); }
            else if (l + 2 == NC) { CPW1(); }
            else { CPW0(); }
            __syncthreads();
            if (kc == 0 && tid < BN)
                advT[tid] = g_cadv[(ch + 2 * tloc) * BN + tid];

            const uint32_t aC = smb + SM_A + (uint32_t)kc * 8192;
            const uint32_t bB = smb + SM_B + (uint32_t)(l & 3) * B_SLOT;
#pragma unroll
            for (int s = 0; s < 4; s++) {
                uint32_t af[2][4], bf[2][4];
#pragma unroll
                for (int mi = 0; mi < 2; mi++) {
                    uint32_t gr = (uint32_t)(((s * 2 + khA) ^ aRowX[mi]) << 4);
                    LDSM4(af[mi], aC + aRowByte[mi] + gr);
                }
#pragma unroll
                for (int nj = 0; nj < 2; nj++) {
                    uint32_t gr = (uint32_t)(((s * 2 + khB) ^ bRowX[nj]) << 4);
                    LDSM4(bf[nj], bB + bRowByte[nj] + gr);
                }
#pragma unroll
                for (int mi = 0; mi < 2; mi++)
#pragma unroll
                    for (int n8 = 0; n8 < 4; n8++)
                        MMA16816(acc[mi][n8], af[mi],
                                 bf[n8 >> 1][(n8 & 1) * 2],
                                 bf[n8 >> 1][(n8 & 1) * 2 + 1]);
            }
        }

        // ---- epilogue (32 EX2/thread) ----
#pragma unroll
        for (int n8 = 0; n8 < 4; n8++) {
            const int nb = wn * 32 + n8 * 8 + (lane & 3) * 2;
            const int a0 = advT[nb], a1 = advT[nb + 1];
#pragma unroll
            for (int mi = 0; mi < 2; mi++)
#pragma unroll
                for (int h = 0; h < 2; h++) {
                    float e0 = fast_exp2(acc[mi][n8][h * 2]);
                    float e1 = fast_exp2(acc[mi][n8][h * 2 + 1]);
                    if (a0 >= 0) sA[mi][h] += e0;
                    if (a1 >= 0) sA[mi][h] += e1;
                    if (a0 == adiR[mi][h]) sP[mi][h] += e0;
                    if (a1 == adiR[mi][h]) sP[mi][h] += e1;
                }
        }
    }

    // ---- reduce over lane&3, then across wn warps ----
#pragma unroll
    for (int mi = 0; mi < 2; mi++)
#pragma unroll
        for (int h = 0; h < 2; h++) {
#pragma unroll
            for (int o = 1; o < 4; o <<= 1) {
                sA[mi][h] += __shfl_xor_sync(0xffffffffu, sA[mi][h], o);
                sP[mi][h] += __shfl_xor_sync(0xffffffffu, sP[mi][h], o);
            }
        }
    if ((lane & 3) == 0) {
#pragma unroll
        for (int mi = 0; mi < 2; mi++)
#pragma unroll
            for (int h = 0; h < 2; h++) {
                int rl = wm * 32 + mi * 16 + h * 8 + (lane >> 2);
                redA[wn * 64 + rl] = sA[mi][h];
                redP[wn * 64 + rl] = sP[mi][h];
            }
    }
    __syncthreads();
    if (tid < BM) {
        float A = redA[tid] + redA[64 + tid] + redA[128 + tid] + redA[192 + tid];
        float P = redP[tid] + redP[64 + tid] + redP[128 + tid] + redP[192 + tid];
        g_rowA[ch * CPAD + brow + tid] = A;
        g_rowP[ch * CPAD + brow + tid] = P;
    }
}

// ---------------- kernel 5: finalize -----------------------------------------
__global__ void finalize_kernel(float* __restrict__ out) {
    const int t = threadIdx.x;   // 1024
    const int cnt = g_cnt;
    float l = 0.f;
#pragma unroll
    for (int i = 0; i < 8; i++) {
        int j = i * 1024 + t;
        if (j < cnt) {
            float A = g_rowA[j] + g_rowA[CPAD + j];
            float P = g_rowP[j] + g_rowP[CPAD + j];
            l += (log2f(A) - log2f(P)) * LN2F;
        }
    }
#pragma unroll
    for (int o = 16; o; o >>= 1) l += __shfl_xor_sync(0xffffffffu, l, o);
    __shared__ float sl[32];
    if ((t & 31) == 0) sl[t >> 5] = l;
    __syncthreads();
    if (t < 32) {
        l = sl[t];
#pragma unroll
        for (int o = 16; o; o >>= 1) l += __shfl_xor_sync(0xffffffffu, l, o);
        if (t == 0) out[0] = l / fmaxf((float)cnt, 1.0f);
    }
}

// ---------------- launch ------------------------------------------------------
extern "C" void kernel_launch(void* const* d_in, const int* in_sizes, int n_in,
                              void* d_out, int out_size) {
    const float* logits = (const float*)d_in[0];
    const float* labels = (const float*)d_in[1];
    const int*   pad    = (const int*)d_in[2];
    const int*   ad     = (const int*)d_in[3];

    cudaFuncSetAttribute(main_kernel, cudaFuncAttributeMaxDynamicSharedMemorySize,
                         DSMEM_BYTES);

    scan_kernel<<<1, 1024>>>(pad);
    scatter_kernel<<<dim3(1024, 2), 256>>>(logits, labels, pad, ad);
    pad_kernel<<<1, 256>>>();
    main_kernel<<<256, 256, DSMEM_BYTES>>>();
    finalize_kernel<<<1, 1024>>>((float*)d_out);
}

// round 13
// speedup vs baseline: 36.6008x; 1.7252x over previous
#include <cuda_runtime.h>
#include <cuda_fp16.h>
#include <cstdint>
#include <math.h>

#define N_ROWS 8192
#define DIM    256
#define CPAD   8320                 /* compacted capacity: 8192 + 128 pad */
#define SCALE  28.85390081777927f   /* (1/0.05) * log2(e) */
#define LN2F   0.6931471805599453f

#define BM     64       /* rows per CTA band (compacted) */
#define BN     128      /* cols per tile (compacted) */
#define KC     64
#define NCH    4        /* column interleave factor */

#define SM_A     0            /* 32 KB: 4 k-chunks x [64 rows x 128B] */
#define SM_B     32768        /* 4 ring slots x 16 KB */
#define B_SLOT   16384
#define SM_ADV   98304        /* 128 ints */
#define SM_REDA  98816        /* 256 floats */
#define SM_REDP  99840        /* 256 floats */
#define DSMEM_BYTES 100864

// ---------------- device scratch ---------------------------------------------
__device__ __half g_qc[CPAD * DIM];     // compacted, q scaled by SCALE
__device__ __half g_kc[CPAD * DIM];     // compacted
__device__ int   g_cadv[CPAD];          // compacted ad (valid rows), -1 in pad
__device__ int   g_cidx[N_ROWS];        // exclusive prefix of validity
__device__ int   g_cnt;                 // number of valid rows
__device__ float g_rowA[NCH * CPAD];
__device__ float g_rowP[NCH * CPAD];

// ---------------- PTX helpers ------------------------------------------------
__device__ __forceinline__ uint32_t smem_u32(const void* p) {
    uint32_t a;
    asm("{ .reg .u64 t; cvta.to.shared.u64 t, %1; cvt.u32.u64 %0, t; }" : "=r"(a) : "l"(p));
    return a;
}
__device__ __forceinline__ float fast_exp2(float x) {
    float y; asm("ex2.approx.ftz.f32 %0, %1;" : "=f"(y) : "f"(x)); return y;
}
#define CPA(dst, src) \
    asm volatile("cp.async.cg.shared.global [%0], [%1], 16;" :: "r"(dst), "l"(src) : "memory")
#define CPC()  asm volatile("cp.async.commit_group;" ::: "memory")
#define CPW2() asm volatile("cp.async.wait_group 2;" ::: "memory")
#define CPW1() asm volatile("cp.async.wait_group 1;" ::: "memory")
#define CPW0() asm volatile("cp.async.wait_group 0;" ::: "memory")

#define LDSM4(r, a) \
    asm volatile("ldmatrix.sync.aligned.m8n8.x4.shared.b16 {%0,%1,%2,%3}, [%4];" \
                 : "=r"((r)[0]), "=r"((r)[1]), "=r"((r)[2]), "=r"((r)[3]) : "r"(a))

#define MMA16816(d, a, b0, b1) \
    asm volatile("mma.sync.aligned.m16n8k16.row.col.f32.f16.f16.f32 " \
                 "{%0,%1,%2,%3}, {%4,%5,%6,%7}, {%8,%9}, {%0,%1,%2,%3};" \
                 : "+f"((d)[0]), "+f"((d)[1]), "+f"((d)[2]), "+f"((d)[3]) \
                 : "r"((a)[0]), "r"((a)[1]), "r"((a)[2]), "r"((a)[3]), \
                   "r"(b0), "r"(b1))

// ---------------- kernel 1: validity scan ------------------------------------
__global__ void scan_kernel(const int* __restrict__ pad) {
    const int t = threadIdx.x;        // 1024
    const int lane = t & 31, warp = t >> 5;
    int4 a = reinterpret_cast<const int4*>(pad)[2 * t];
    int4 b = reinterpret_cast<const int4*>(pad)[2 * t + 1];
    int v[8] = {a.x ? 1 : 0, a.y ? 1 : 0, a.z ? 1 : 0, a.w ? 1 : 0,
                b.x ? 1 : 0, b.y ? 1 : 0, b.z ? 1 : 0, b.w ? 1 : 0};
    int pre[8], s = 0;
#pragma unroll
    for (int i = 0; i < 8; i++) { pre[i] = s; s += v[i]; }
    int incl = s;
#pragma unroll
    for (int o = 1; o < 32; o <<= 1) {
        int n = __shfl_up_sync(0xffffffffu, incl, o);
        if (lane >= o) incl += n;
    }
    __shared__ int wtot[32], woff[32];
    if (lane == 31) wtot[warp] = incl;
    __syncthreads();
    if (t < 32) {
        int w = wtot[t], wi = w;
#pragma unroll
        for (int o = 1; o < 32; o <<= 1) {
            int n = __shfl_up_sync(0xffffffffu, wi, o);
            if (t >= o) wi += n;
        }
        woff[t] = wi - w;
        if (t == 31) g_cnt = wi;
    }
    __syncthreads();
    int base = woff[warp] + incl - s;
#pragma unroll
    for (int i = 0; i < 8; i++) g_cidx[8 * t + i] = base + pre[i];
}

// ---------------- kernel 2: normalize + scatter-compact (+tail pad) ----------
__global__ void scatter_kernel(const float* __restrict__ logits,
                               const float* __restrict__ labels,
                               const int* __restrict__ pad,
                               const int* __restrict__ ad) {
    const int lane = threadIdx.x & 31;
    const int warp = threadIdx.x >> 5;
    const int row  = blockIdx.x * 8 + warp;
    if (!pad[row]) {
        // i-th invalid row zero-fills compacted pad slot cnt+i (i < 128).
        const int i = row - g_cidx[row];
        if (i < 128) {
            const int j = g_cnt + i;
            __half* dst = blockIdx.y ? g_kc : g_qc;
            const uint4 z = {0u, 0u, 0u, 0u};
            *reinterpret_cast<uint4*>(dst + (size_t)j * DIM + lane * 8) = z;
            if (blockIdx.y == 0 && lane == 0) g_cadv[j] = -1;
        }
        return;
    }
    const int j = g_cidx[row];
    const float* src = blockIdx.y ? labels : logits;
    __half* dst = blockIdx.y ? g_kc : g_qc;
    const float post = blockIdx.y ? 1.0f : SCALE;
    const float* rp = src + (size_t)row * DIM + lane * 8;
    float4 v0 = *reinterpret_cast<const float4*>(rp);
    float4 v1 = *reinterpret_cast<const float4*>(rp + 4);
    float ss = v0.x*v0.x + v0.y*v0.y + v0.z*v0.z + v0.w*v0.w
             + v1.x*v1.x + v1.y*v1.y + v1.z*v1.z + v1.w*v1.w;
#pragma unroll
    for (int o = 16; o; o >>= 1) ss += __shfl_xor_sync(0xffffffffu, ss, o);
    float s = (1.0f / fmaxf(sqrtf(ss), 1e-12f)) * post;
    __half2 h0 = __floats2half2_rn(v0.x * s, v0.y * s);
    __half2 h1 = __floats2half2_rn(v0.z * s, v0.w * s);
    __half2 h2 = __floats2half2_rn(v1.x * s, v1.y * s);
    __half2 h3 = __floats2half2_rn(v1.z * s, v1.w * s);
    uint4 pk;
    pk.x = *reinterpret_cast<uint32_t*>(&h0);
    pk.y = *reinterpret_cast<uint32_t*>(&h1);
    pk.z = *reinterpret_cast<uint32_t*>(&h2);
    pk.w = *reinterpret_cast<uint32_t*>(&h3);
    *reinterpret_cast<uint4*>(dst + (size_t)j * DIM + lane * 8) = pk;
    if (blockIdx.y == 0 && lane == 0) g_cadv[j] = ad[row];
}

// ---------------- B chunk issue (cp.async, swizzled) --------------------------
__device__ __forceinline__ void issue_b(uint32_t smb, int l, int ch, int tid) {
    const int tile = ch + ((l >> 2) << 2);       // ch, ch+4, ch+8, ...
    const int col0 = tile * BN;
    const int koff = (l & 3) * KC;
    uint32_t slot = smb + SM_B + (uint32_t)(l & 3) * B_SLOT;
#pragma unroll
    for (int r = 0; r < 4; r++) {
        int idx = r * 256 + tid;
        int n = idx >> 3;
        int g = idx & 7;
        uint32_t dst = slot + (uint32_t)(n * 128 + ((g ^ (n & 7)) << 4));
        CPA(dst, g_kc + (size_t)(col0 + n) * DIM + koff + g * 8);
    }
    CPC();
}

// ---------------- kernel 3: fused compacted GEMM + masked-exp ----------------
__global__ __launch_bounds__(256, 2) void main_kernel() {
    extern __shared__ char dsm[];
    const uint32_t smb = smem_u32(dsm);
    const int tid  = threadIdx.x;
    const int lane = tid & 31;
    const int wid  = tid >> 5;
    const int wm   = wid >> 2;        // 0..1 (32-row half of 64)
    const int wn   = wid & 3;         // 0..3 (32-col quarter of 128)
    const int band = blockIdx.x >> 2;
    const int ch   = blockIdx.x & 3;
    const int brow = band * BM;
    const int cnt  = g_cnt;
    if (brow >= cnt) return;
    const int T   = (cnt + 127) >> 7;
    const int myT = (T - ch + 3) >> 2;
    if (myT == 0) {
        if (tid < BM) {
            g_rowA[ch * CPAD + brow + tid] = 0.f;
            g_rowP[ch * CPAD + brow + tid] = 0.f;
        }
        return;
    }
    const int NC = 4 * myT;

    int*   advT = reinterpret_cast<int*>(dsm + SM_ADV);
    float* redA = reinterpret_cast<float*>(dsm + SM_REDA);
    float* redP = reinterpret_cast<float*>(dsm + SM_REDP);

    const int matA = lane >> 3;
    const int rowAoff = (lane & 7) + ((matA & 1) << 3);
    const int khA  = matA >> 1;
    const int nrowOff = ((lane >> 4) << 3) + (lane & 7);
    const int khB  = (lane >> 3) & 1;

    uint32_t aRowByte[2]; int aRowX[2];
#pragma unroll
    for (int mi = 0; mi < 2; mi++) {
        int row = wm * 32 + mi * 16 + rowAoff;
        aRowByte[mi] = (uint32_t)(row * 128);
        aRowX[mi] = row & 7;
    }
    uint32_t bRowByte[2]; int bRowX[2];
#pragma unroll
    for (int nj = 0; nj < 2; nj++) {
        int nrow = wn * 32 + nj * 16 + nrowOff;
        bRowByte[nj] = (uint32_t)(nrow * 128);
        bRowX[nj] = nrow & 7;
    }

    int adiR[2][2];
#pragma unroll
    for (int mi = 0; mi < 2; mi++)
#pragma unroll
        for (int h = 0; h < 2; h++)
            adiR[mi][h] = g_cadv[brow + wm * 32 + mi * 16 + h * 8 + (lane >> 2)];

    // ---- prologue: A band (32 KB), then B chunks 0,1 ----
#pragma unroll
    for (int r = 0; r < 8; r++) {
        int idx = r * 256 + tid;
        int m = idx >> 5;          // row 0..63
        int g = idx & 31;          // 16B granule
        uint32_t dst = smb + SM_A + (uint32_t)((g >> 3) * 8192 + m * 128 +
                                               (((g & 7) ^ (m & 7)) << 4));
        CPA(dst, g_qc + (size_t)(brow + m) * DIM + g * 8);
    }
    CPC();
    issue_b(smb, 0, ch, tid);
    issue_b(smb, 1, ch, tid);    // NC >= 4 always when myT >= 1

    float sA[2][2], sP[2][2];
#pragma unroll
    for (int mi = 0; mi < 2; mi++)
#pragma unroll
        for (int h = 0; h < 2; h++) { sA[mi][h] = 0.f; sP[mi][h] = 0.f; }

#pragma unroll 1
    for (int tloc = 0; tloc < myT; tloc++) {
        float acc[2][4][4];
#pragma unroll
        for (int mi = 0; mi < 2; mi++)
#pragma unroll
            for (int n8 = 0; n8 < 4; n8++)
#pragma unroll
                for (int r = 0; r < 4; r++) acc[mi][n8][r] = 0.f;

#pragma unroll
        for (int kc = 0; kc < 4; kc++) {
            const int l = tloc * 4 + kc;
            if (l + 2 < NC) { issue_b(smb, l + 2, ch, tid); CPW2(); }
            else if (l + 2 == NC) { CPW1(); }
            else { CPW0(); }
            __syncthreads();
            if (kc == 0 && tid < BN)
                advT[tid] = g_cadv[(ch + 4 * tloc) * BN + tid];

            const uint32_t aC = smb + SM_A + (uint32_t)kc * 8192;
            const uint32_t bB = smb + SM_B + (uint32_t)(l & 3) * B_SLOT;
#pragma unroll
            for (int s = 0; s < 4; s++) {
                uint32_t af[2][4], bf[2][4];
#pragma unroll
                for (int mi = 0; mi < 2; mi++) {
                    uint32_t gr = (uint32_t)(((s * 2 + khA) ^ aRowX[mi]) << 4);
                    LDSM4(af[mi], aC + aRowByte[mi] + gr);
                }
#pragma unroll
                for (int nj = 0; nj < 2; nj++) {
                    uint32_t gr = (uint32_t)(((s * 2 + khB) ^ bRowX[nj]) << 4);
                    LDSM4(bf[nj], bB + bRowByte[nj] + gr);
                }
#pragma unroll
                for (int mi = 0; mi < 2; mi++)
#pragma unroll
                    for (int n8 = 0; n8 < 4; n8++)
                        MMA16816(acc[mi][n8], af[mi],
                                 bf[n8 >> 1][(n8 & 1) * 2],
                                 bf[n8 >> 1][(n8 & 1) * 2 + 1]);
            }
        }

        // ---- epilogue (32 EX2/thread) ----
#pragma unroll
        for (int n8 = 0; n8 < 4; n8++) {
            const int nb = wn * 32 + n8 * 8 + (lane & 3) * 2;
            const int a0 = advT[nb], a1 = advT[nb + 1];
#pragma unroll
            for (int mi = 0; mi < 2; mi++)
#pragma unroll
                for (int h = 0; h < 2; h++) {
                    float e0 = fast_exp2(acc[mi][n8][h * 2]);
                    float e1 = fast_exp2(acc[mi][n8][h * 2 + 1]);
                    if (a0 >= 0) sA[mi][h] += e0;
                    if (a1 >= 0) sA[mi][h] += e1;
                    if (a0 == adiR[mi][h]) sP[mi][h] += e0;
                    if (a1 == adiR[mi][h]) sP[mi][h] += e1;
                }
        }
    }

    // ---- reduce over lane&3, then across wn warps ----
#pragma unroll
    for (int mi = 0; mi < 2; mi++)
#pragma unroll
        for (int h = 0; h < 2; h++) {
#pragma unroll
            for (int o = 1; o < 4; o <<= 1) {
                sA[mi][h] += __shfl_xor_sync(0xffffffffu, sA[mi][h], o);
                sP[mi][h] += __shfl_xor_sync(0xffffffffu, sP[mi][h], o);
            }
        }
    if ((lane & 3) == 0) {
#pragma unroll
        for (int mi = 0; mi < 2; mi++)
#pragma unroll
            for (int h = 0; h < 2; h++) {
                int rl = wm * 32 + mi * 16 + h * 8 + (lane >> 2);
                redA[wn * 64 + rl] = sA[mi][h];
                redP[wn * 64 + rl] = sP[mi][h];
            }
    }
    __syncthreads();
    if (tid < BM) {
        float A = redA[tid] + redA[64 + tid] + redA[128 + tid] + redA[192 + tid];
        float P = redP[tid] + redP[64 + tid] + redP[128 + tid] + redP[192 + tid];
        g_rowA[ch * CPAD + brow + tid] = A;
        g_rowP[ch * CPAD + brow + tid] = P;
    }
}

// ---------------- kernel 4: finalize -----------------------------------------
__global__ void finalize_kernel(float* __restrict__ out) {
    const int t = threadIdx.x;   // 1024
    const int cnt = g_cnt;
    float l = 0.f;
#pragma unroll
    for (int i = 0; i < 8; i++) {
        int j = i * 1024 + t;
        if (j < cnt) {
            float A = g_rowA[j] + g_rowA[CPAD + j] + g_rowA[2 * CPAD + j] + g_rowA[3 * CPAD + j];
            float P = g_rowP[j] + g_rowP[CPAD + j] + g_rowP[2 * CPAD + j] + g_rowP[3 * CPAD + j];
            l += (log2f(A) - log2f(P)) * LN2F;
        }
    }
#pragma unroll
    for (int o = 16; o; o >>= 1) l += __shfl_xor_sync(0xffffffffu, l, o);
    __shared__ float sl[32];
    if ((t & 31) == 0) sl[t >> 5] = l;
    __syncthreads();
    if (t < 32) {
        l = sl[t];
#pragma unroll
        for (int o = 16; o; o >>= 1) l += __shfl_xor_sync(0xffffffffu, l, o);
        if (t == 0) out[0] = l / fmaxf((float)cnt, 1.0f);
    }
}

// ---------------- launch ------------------------------------------------------
extern "C" void kernel_launch(void* const* d_in, const int* in_sizes, int n_in,
                              void* d_out, int out_size) {
    const float* logits = (const float*)d_in[0];
    const float* labels = (const float*)d_in[1];
    const int*   pad    = (const int*)d_in[2];
    const int*   ad     = (const int*)d_in[3];

    cudaFuncSetAttribute(main_kernel, cudaFuncAttributeMaxDynamicSharedMemorySize,
                         DSMEM_BYTES);

    scan_kernel<<<1, 1024>>>(pad);
    scatter_kernel<<<dim3(1024, 2), 256>>>(logits, labels, pad, ad);
    main_kernel<<<512, 256, DSMEM_BYTES>>>();
    finalize_kernel<<<1, 1024>>>((float*)d_out);
}